// round 1
// baseline (speedup 1.0000x reference)
#include <cuda_runtime.h>

#define BB 16
#define NN 2048
#define NCTX 2047
#define EMB 64
#define DIN 160
#define NLAYERS 3
#define ACH 16
#define CHN 128
#define CC 128

// Scratch (allocation-free rule: device globals)
__device__ float g_Rpart[BB * ACH * 96 * 32];   // per-(batch,chunk) partial R = [G;C]
__device__ float g_P[BB * 64 * 32];             // P[c][j] per batch

// ---------------- Kernel A: R[b] = x[0:96,:2047] @ x[0:32,:2047]^T (chunked partials) ----
extern "C" __global__ void kA(const float* __restrict__ x) {
    extern __shared__ float sx[]; // [96][129]
    const int b = blockIdx.y, ch = blockIdx.x, tid = threadIdx.x;
    const int n0 = ch * CHN;
    const int count = min(CHN, NCTX - n0);
    const float* xb = x + (size_t)b * DIN * NN;
    for (int i = tid; i < 96 * CHN; i += 256) {
        int r = i >> 7, n = i & 127;
        sx[r * 129 + n] = (n < count) ? xb[r * NN + n0 + n] : 0.f;
    }
    __syncthreads();
    const int tc = tid & 15, tr = tid >> 4;
    float acc[6][2];
#pragma unroll
    for (int a = 0; a < 6; a++) { acc[a][0] = 0.f; acc[a][1] = 0.f; }
#pragma unroll 4
    for (int n = 0; n < CHN; n++) {
        float bv0 = sx[(tc * 2 + 0) * 129 + n];
        float bv1 = sx[(tc * 2 + 1) * 129 + n];
#pragma unroll
        for (int rr = 0; rr < 6; rr++) {
            float av = sx[(tr * 6 + rr) * 129 + n];
            acc[rr][0] += av * bv0;
            acc[rr][1] += av * bv1;
        }
    }
    float* outp = g_Rpart + (size_t)(b * ACH + ch) * (96 * 32);
#pragma unroll
    for (int rr = 0; rr < 6; rr++) {
        outp[(tr * 6 + rr) * 32 + tc * 2 + 0] = acc[rr][0];
        outp[(tr * 6 + rr) * 32 + tc * 2 + 1] = acc[rr][1];
    }
}

// ---------------- Kernel B: per-batch tiny algebra -> P ----------------
extern "C" __global__ void kB(const float* __restrict__ alpha,
                              const float* __restrict__ kp_,
                              const float* __restrict__ E,
                              const float* __restrict__ M) {
    extern __shared__ float smb[];
    float* sE   = smb;           // 4096
    float* sM   = sE + 4096;     // 4096
    float* sR   = sM + 4096;     // 3072  (rows 0..31 = G, rows 32..95 = C)
    float* sW   = sR + 3072;     // 2048
    float* sS   = sW + 2048;     // 2048
    float* sT   = sS + 2048;     // 2048
    float* sSum = sT + 2048;     // 2048
    const int b = blockIdx.x, tid = threadIdx.x; // 512 threads
    for (int i = tid; i < 4096; i += 512) { sE[i] = E[i]; sM[i] = M[i]; }
    for (int i = tid; i < 3072; i += 512) {
        float s = 0.f;
        const float* rp = g_Rpart + (size_t)b * ACH * 3072 + i;
#pragma unroll
        for (int c = 0; c < ACH; c++) s += rp[c * 3072];
        sR[i] = s;
    }
    for (int i = tid; i < 2048; i += 512) sSum[i] = 0.f;
    __syncthreads();

    const int i0 = tid >> 3;
    const int j0 = (tid & 7) * 4;
    const float* sC = sR + 32 * 32;

    // W0 = E @ C
    {
        float a0 = 0, a1 = 0, a2 = 0, a3 = 0;
#pragma unroll
        for (int k = 0; k < 64; k++) {
            float e = sE[i0 * 64 + k];
            float4 cv = *(const float4*)(sC + k * 32 + j0);
            a0 += e * cv.x; a1 += e * cv.y; a2 += e * cv.z; a3 += e * cv.w;
        }
        *(float4*)(sW + i0 * 32 + j0) = make_float4(a0, a1, a2, a3);
    }
    __syncthreads();

    const float kp = kp_[0];
    for (int l = 0; l < NLAYERS; l++) {
        float sc = kp * alpha[l * EMB + i0] * (1.0f / (float)NCTX);
        {
            float4 wv = *(const float4*)(sW + i0 * 32 + j0);
            float4 sv = make_float4(sc * wv.x, sc * wv.y, sc * wv.z, sc * wv.w);
            *(float4*)(sS + i0 * 32 + j0) = sv;
            float4 su = *(const float4*)(sSum + i0 * 32 + j0);
            su.x += sv.x; su.y += sv.y; su.z += sv.z; su.w += sv.w;
            *(float4*)(sSum + i0 * 32 + j0) = su;
        }
        __syncthreads();
        if (l < NLAYERS - 1) {
            // T = M @ S
            float a0 = 0, a1 = 0, a2 = 0, a3 = 0;
#pragma unroll
            for (int k = 0; k < 64; k++) {
                float m = sM[i0 * 64 + k];
                float4 sv = *(const float4*)(sS + k * 32 + j0);
                a0 += m * sv.x; a1 += m * sv.y; a2 += m * sv.z; a3 += m * sv.w;
            }
            *(float4*)(sT + i0 * 32 + j0) = make_float4(a0, a1, a2, a3);
            __syncthreads();
            // W += T @ G
            a0 = 0; a1 = 0; a2 = 0; a3 = 0;
#pragma unroll
            for (int p = 0; p < 32; p++) {
                float t = sT[i0 * 32 + p];
                float4 gv = *(const float4*)(sR + p * 32 + j0);
                a0 += t * gv.x; a1 += t * gv.y; a2 += t * gv.z; a3 += t * gv.w;
            }
            float4 wv = *(const float4*)(sW + i0 * 32 + j0);
            wv.x += a0; wv.y += a1; wv.z += a2; wv.w += a3;
            *(float4*)(sW + i0 * 32 + j0) = wv;
            __syncthreads();
        }
    }
    // P[c][j] = sum_d E[d][c] * Sum[d][j]  (c = i0)
    {
        float a0 = 0, a1 = 0, a2 = 0, a3 = 0;
#pragma unroll
        for (int d = 0; d < 64; d++) {
            float e = sE[d * 64 + i0];
            float4 sv = *(const float4*)(sSum + d * 32 + j0);
            a0 += e * sv.x; a1 += e * sv.y; a2 += e * sv.z; a3 += e * sv.w;
        }
        *(float4*)(g_P + (size_t)(b * 64 + i0) * 32 + j0) = make_float4(a0, a1, a2, a3);
    }
}

// ---------------- Kernel C: logits = U^T @ V, softmax, writes ----------------
extern "C" __global__ void kC(const float* __restrict__ x,
                              const float* __restrict__ E,
                              float* __restrict__ out) {
    extern __shared__ float smc[];
    float* sU   = smc;          // 96*64
    float* sV   = sU + 6144;    // 96*128 (overlaid by slog 64*129 after GEMM)
    float* smx  = sV + 12288;   // 128
    float* ssum = smx + 128;    // 128
    float* slog = sV;
    const int b = blockIdx.y, chn = blockIdx.x, tid = threadIdx.x;
    const int n0 = chn * CC;
    const float* xb = x + (size_t)b * DIN * NN;
    // U[k][c]: k<64 -> E[k][c]; k=64+j -> P[c][j]
    for (int i = tid; i < 96 * 64; i += 256) {
        int k = i >> 6, c = i & 63;
        sU[i] = (k < 64) ? E[i] : g_P[(size_t)(b * 64 + c) * 32 + (k - 64)];
    }
    // V[k][n]: k<64 -> f0 row (96+k); k=64+j -> xq row j
    for (int i = tid; i < 96 * CC; i += 256) {
        int k = i >> 7, n = i & 127;
        int row = (k < 64) ? (96 + k) : (k - 64);
        sV[i] = xb[row * NN + n0 + n];
    }
    __syncthreads();
    const int tc = tid & 15, tn = tid >> 4;
    const int c0 = tc * 4, nb = tn * 8;
    float acc[4][8];
#pragma unroll
    for (int a = 0; a < 4; a++)
#pragma unroll
        for (int q = 0; q < 8; q++) acc[a][q] = 0.f;
#pragma unroll 2
    for (int k = 0; k < 96; k++) {
        float4 u  = *(const float4*)(sU + k * 64 + c0);
        float4 v0 = *(const float4*)(sV + k * 128 + nb);
        float4 v1 = *(const float4*)(sV + k * 128 + nb + 4);
        float uu[4] = {u.x, u.y, u.z, u.w};
        float vv[8] = {v0.x, v0.y, v0.z, v0.w, v1.x, v1.y, v1.z, v1.w};
#pragma unroll
        for (int a = 0; a < 4; a++)
#pragma unroll
            for (int q = 0; q < 8; q++) acc[a][q] += uu[a] * vv[q];
    }
    __syncthreads();  // all sV reads done before overlay
#pragma unroll
    for (int a = 0; a < 4; a++)
#pragma unroll
        for (int q = 0; q < 8; q++)
            slog[(c0 + a) * 129 + nb + q] = acc[a][q];
    __syncthreads();
    // coalesced logits write + per-column max
    float* gl = out + ((size_t)(b * NN + n0)) * 64;
    for (int e = tid; e < CC * 64; e += 256) {
        int col = e >> 6, c = e & 63;
        gl[e] = slog[c * 129 + col];
    }
    if (tid < CC) {
        float m = -1e30f;
#pragma unroll
        for (int c = 0; c < 64; c++) m = fmaxf(m, slog[c * 129 + tid]);
        smx[tid] = m;
    }
    __syncthreads();
    for (int e = tid; e < CC * 64; e += 256) {
        int col = e >> 6, c = e & 63;
        slog[c * 129 + col] = __expf(slog[c * 129 + col] - smx[col]);
    }
    __syncthreads();
    if (tid < CC) {
        float s = 0.f;
#pragma unroll
        for (int c = 0; c < 64; c++) s += slog[c * 129 + tid];
        ssum[tid] = 1.0f / s;
    }
    __syncthreads();
    float* gp = out + (size_t)BB * NN * 64 + ((size_t)(b * NN + n0)) * 64;
    for (int e = tid; e < CC * 64; e += 256) {
        int col = e >> 6, c = e & 63;
        gp[e] = slog[c * 129 + col] * ssum[col];
    }
}

extern "C" void kernel_launch(void* const* d_in, const int* in_sizes, int n_in,
                              void* d_out, int out_size) {
    const float* x     = (const float*)d_in[0];
    const float* alpha = (const float*)d_in[1];
    const float* kp    = (const float*)d_in[2];
    const float* E     = (const float*)d_in[3];
    const float* M     = (const float*)d_in[4];
    float* out = (float*)d_out;

    const int smemA = 96 * 129 * 4;                 // 49,536 B
    const int smemB = (4096*2 + 3072 + 2048*4) * 4; // 77,824 B
    const int smemC = (6144 + 12288 + 256) * 4;     // 74,752 B
    cudaFuncSetAttribute(kA, cudaFuncAttributeMaxDynamicSharedMemorySize, smemA);
    cudaFuncSetAttribute(kB, cudaFuncAttributeMaxDynamicSharedMemorySize, smemB);
    cudaFuncSetAttribute(kC, cudaFuncAttributeMaxDynamicSharedMemorySize, smemC);

    kA<<<dim3(ACH, BB), 256, smemA>>>(x);
    kB<<<BB, 512, smemB>>>(alpha, kp, E, M);
    kC<<<dim3(NN / CC, BB), 256, smemC>>>(x, E, out);
}

// round 3
// speedup vs baseline: 1.1362x; 1.1362x over previous
#include <cuda_runtime.h>

#define BB 16
#define NN 2048
#define NCTX 2047
#define EMB 64
#define DIN 160
#define NLAYERS 3
#define ACH 32
#define CHN 64
#define CC 128

// Scratch (allocation-free rule: device globals)
__device__ float g_Rpart[BB * ACH * 96 * 32];   // per-(batch,chunk) partial R = [G;C]
__device__ float g_P[BB * 64 * 32];             // P[c][j] per batch

// ---------------- Kernel A: R[b] = x[0:96,:2047] @ x[0:32,:2047]^T (chunked partials) ----
extern "C" __global__ void kA(const float* __restrict__ x) {
    extern __shared__ float sx[]; // [96][65]
    const int b = blockIdx.y, ch = blockIdx.x, tid = threadIdx.x;
    const int n0 = ch * CHN;
    const int count = min(CHN, NCTX - n0);
    const float* xb = x + (size_t)b * DIN * NN;
    for (int i = tid; i < 96 * CHN; i += 256) {
        int r = i >> 6, n = i & 63;
        sx[r * 65 + n] = (n < count) ? xb[r * NN + n0 + n] : 0.f;
    }
    __syncthreads();
    const int tc = tid & 15, tr = tid >> 4;
    float acc[6][2];
#pragma unroll
    for (int a = 0; a < 6; a++) { acc[a][0] = 0.f; acc[a][1] = 0.f; }
#pragma unroll 4
    for (int n = 0; n < CHN; n++) {
        float bv0 = sx[(tc * 2 + 0) * 65 + n];
        float bv1 = sx[(tc * 2 + 1) * 65 + n];
#pragma unroll
        for (int rr = 0; rr < 6; rr++) {
            float av = sx[(tr * 6 + rr) * 65 + n];
            acc[rr][0] += av * bv0;
            acc[rr][1] += av * bv1;
        }
    }
    float* outp = g_Rpart + (size_t)(b * ACH + ch) * (96 * 32);
#pragma unroll
    for (int rr = 0; rr < 6; rr++) {
        outp[(tr * 6 + rr) * 32 + tc * 2 + 0] = acc[rr][0];
        outp[(tr * 6 + rr) * 32 + tc * 2 + 1] = acc[rr][1];
    }
}

// ---------------- Kernel B: per-batch tiny algebra -> P ----------------
extern "C" __global__ void kB(const float* __restrict__ alpha,
                              const float* __restrict__ kp_,
                              const float* __restrict__ E,
                              const float* __restrict__ M) {
    extern __shared__ float smb[];
    float* sE   = smb;           // 4096
    float* sM   = sE + 4096;     // 4096
    float* sR   = sM + 4096;     // 3072  (rows 0..31 = G, rows 32..95 = C)
    float* sW   = sR + 3072;     // 2048
    float* sS   = sW + 2048;     // 2048
    float* sT   = sS + 2048;     // 2048
    float* sSum = sT + 2048;     // 2048
    const int b = blockIdx.x, tid = threadIdx.x; // 512 threads
    for (int i = tid; i < 4096; i += 512) { sE[i] = E[i]; sM[i] = M[i]; }
    for (int i = tid; i < 3072; i += 512) {
        float s = 0.f;
        const float* rp = g_Rpart + (size_t)b * ACH * 3072 + i;
#pragma unroll
        for (int c = 0; c < ACH; c++) s += rp[c * 3072];
        sR[i] = s;
    }
    for (int i = tid; i < 2048; i += 512) sSum[i] = 0.f;
    __syncthreads();

    const int i0 = tid >> 3;
    const int j0 = (tid & 7) * 4;
    const float* sC = sR + 32 * 32;

    // W0 = E @ C
    {
        float a0 = 0, a1 = 0, a2 = 0, a3 = 0;
#pragma unroll
        for (int k = 0; k < 64; k++) {
            float e = sE[i0 * 64 + k];
            float4 cv = *(const float4*)(sC + k * 32 + j0);
            a0 += e * cv.x; a1 += e * cv.y; a2 += e * cv.z; a3 += e * cv.w;
        }
        *(float4*)(sW + i0 * 32 + j0) = make_float4(a0, a1, a2, a3);
    }
    __syncthreads();

    const float kp = kp_[0];
    for (int l = 0; l < NLAYERS; l++) {
        float sc = kp * alpha[l * EMB + i0] * (1.0f / (float)NCTX);
        {
            float4 wv = *(const float4*)(sW + i0 * 32 + j0);
            float4 sv = make_float4(sc * wv.x, sc * wv.y, sc * wv.z, sc * wv.w);
            *(float4*)(sS + i0 * 32 + j0) = sv;
            float4 su = *(const float4*)(sSum + i0 * 32 + j0);
            su.x += sv.x; su.y += sv.y; su.z += sv.z; su.w += sv.w;
            *(float4*)(sSum + i0 * 32 + j0) = su;
        }
        __syncthreads();
        if (l < NLAYERS - 1) {
            // T = M @ S
            float a0 = 0, a1 = 0, a2 = 0, a3 = 0;
#pragma unroll
            for (int k = 0; k < 64; k++) {
                float m = sM[i0 * 64 + k];
                float4 sv = *(const float4*)(sS + k * 32 + j0);
                a0 += m * sv.x; a1 += m * sv.y; a2 += m * sv.z; a3 += m * sv.w;
            }
            *(float4*)(sT + i0 * 32 + j0) = make_float4(a0, a1, a2, a3);
            __syncthreads();
            // W += T @ G
            a0 = 0; a1 = 0; a2 = 0; a3 = 0;
#pragma unroll
            for (int p = 0; p < 32; p++) {
                float t = sT[i0 * 32 + p];
                float4 gv = *(const float4*)(sR + p * 32 + j0);
                a0 += t * gv.x; a1 += t * gv.y; a2 += t * gv.z; a3 += t * gv.w;
            }
            float4 wv = *(const float4*)(sW + i0 * 32 + j0);
            wv.x += a0; wv.y += a1; wv.z += a2; wv.w += a3;
            *(float4*)(sW + i0 * 32 + j0) = wv;
            __syncthreads();
        }
    }
    // P[c][j] = sum_d E[d][c] * Sum[d][j]  (c = i0)
    {
        float a0 = 0, a1 = 0, a2 = 0, a3 = 0;
#pragma unroll
        for (int d = 0; d < 64; d++) {
            float e = sE[d * 64 + i0];
            float4 sv = *(const float4*)(sSum + d * 32 + j0);
            a0 += e * sv.x; a1 += e * sv.y; a2 += e * sv.z; a3 += e * sv.w;
        }
        *(float4*)(g_P + (size_t)(b * 64 + i0) * 32 + j0) = make_float4(a0, a1, a2, a3);
    }
}

// ---------------- Kernel C: logits = U^T @ V, softmax (shfl), direct stores ----------------
extern "C" __global__ void kC(const float* __restrict__ x,
                              const float* __restrict__ E,
                              float* __restrict__ out) {
    extern __shared__ float smc[];
    float* sU = smc;           // 96*64
    float* sV = sU + 6144;     // 96*128
    const int b = blockIdx.y, chn = blockIdx.x, tid = threadIdx.x;
    const int n0 = chn * CC;
    const float* xb = x + (size_t)b * DIN * NN;
    // U[k][c]: k<64 -> E[k][c]; k=64+j -> P[c][j]
    for (int i = tid; i < 96 * 64; i += 256) {
        int k = i >> 6, c = i & 63;
        sU[i] = (k < 64) ? E[i] : g_P[(size_t)(b * 64 + c) * 32 + (k - 64)];
    }
    // V[k][n]: k<64 -> f0 row (96+k); k=64+j -> xq row j
    for (int i = tid; i < 96 * CC; i += 256) {
        int k = i >> 7, n = i & 127;
        int row = (k < 64) ? (96 + k) : (k - 64);
        sV[i] = xb[row * NN + n0 + n];
    }
    __syncthreads();
    const int tc = tid & 15, tn = tid >> 4;
    const int c0 = tc * 4, nb = tn * 8;
    float acc[4][8];
#pragma unroll
    for (int a = 0; a < 4; a++)
#pragma unroll
        for (int q = 0; q < 8; q++) acc[a][q] = 0.f;
#pragma unroll 2
    for (int k = 0; k < 96; k++) {
        float4 u  = *(const float4*)(sU + k * 64 + c0);
        float4 v0 = *(const float4*)(sV + k * 128 + nb);
        float4 v1 = *(const float4*)(sV + k * 128 + nb + 4);
        float uu[4] = {u.x, u.y, u.z, u.w};
        float vv[8] = {v0.x, v0.y, v0.z, v0.w, v1.x, v1.y, v1.z, v1.w};
#pragma unroll
        for (int a = 0; a < 4; a++)
#pragma unroll
            for (int q = 0; q < 8; q++) acc[a][q] += uu[a] * vv[q];
    }
    // ---- logits: direct register -> global (16 lanes x float4 = 256B per column) ----
    float* gl = out + ((size_t)(b * NN + n0)) * 64;
#pragma unroll
    for (int q = 0; q < 8; q++) {
        *(float4*)(gl + (size_t)(nb + q) * 64 + c0) =
            make_float4(acc[0][q], acc[1][q], acc[2][q], acc[3][q]);
    }
    // ---- softmax over c (64 classes spread over this 16-lane group) via shfl ----
    float* gp = out + (size_t)BB * NN * 64 + ((size_t)(b * NN + n0)) * 64;
#pragma unroll
    for (int q = 0; q < 8; q++) {
        float m = fmaxf(fmaxf(acc[0][q], acc[1][q]), fmaxf(acc[2][q], acc[3][q]));
#pragma unroll
        for (int off = 1; off < 16; off <<= 1)
            m = fmaxf(m, __shfl_xor_sync(0xffffffffu, m, off));
        float e0 = __expf(acc[0][q] - m);
        float e1 = __expf(acc[1][q] - m);
        float e2 = __expf(acc[2][q] - m);
        float e3 = __expf(acc[3][q] - m);
        float s = e0 + e1 + e2 + e3;
#pragma unroll
        for (int off = 1; off < 16; off <<= 1)
            s += __shfl_xor_sync(0xffffffffu, s, off);
        float inv = __frcp_rn(s);
        *(float4*)(gp + (size_t)(nb + q) * 64 + c0) =
            make_float4(e0 * inv, e1 * inv, e2 * inv, e3 * inv);
    }
}

extern "C" void kernel_launch(void* const* d_in, const int* in_sizes, int n_in,
                              void* d_out, int out_size) {
    const float* x     = (const float*)d_in[0];
    const float* alpha = (const float*)d_in[1];
    const float* kp    = (const float*)d_in[2];
    const float* E     = (const float*)d_in[3];
    const float* M     = (const float*)d_in[4];
    float* out = (float*)d_out;

    const int smemA = 96 * 65 * 4;                  // 24,960 B
    const int smemB = (4096*2 + 3072 + 2048*4) * 4; // 77,824 B
    const int smemC = (6144 + 12288) * 4;           // 73,728 B
    cudaFuncSetAttribute(kA, cudaFuncAttributeMaxDynamicSharedMemorySize, smemA);
    cudaFuncSetAttribute(kB, cudaFuncAttributeMaxDynamicSharedMemorySize, smemB);
    cudaFuncSetAttribute(kC, cudaFuncAttributeMaxDynamicSharedMemorySize, smemC);

    kA<<<dim3(ACH, BB), 256, smemA>>>(x);
    kB<<<BB, 512, smemB>>>(alpha, kp, E, M);
    kC<<<dim3(NN / CC, BB), 256, smemC>>>(x, E, out);
}